// round 13
// baseline (speedup 1.0000x reference)
#include <cuda_runtime.h>
#include <cuda_fp16.h>
#include <cstdint>
#include <cstdio>

#define NN 50000
#define NE 200000
#define HH 512
#define G3 1536

// ---------------- device scratch (static, no allocation) ----------------
__device__ int g_is64;
__device__ int g_src[NE];
__device__ int g_dst[NE];
__device__ int g_inp[NN];
__device__ int g_rowptr[NN + 1];
__device__ int g_cursor[NN];
__device__ int g_csr[NE];
__device__ int g_bsum[64];
__device__ unsigned long long g_ts[16][2];
__device__ __align__(128) __half g_x0h[(size_t)NN * HH]; // fp16 node states
__device__ __align__(128) __half g_x1h[(size_t)NN * HH];
__device__ __align__(128) __half g_Sh[(size_t)NN * HH];
// g_Bh[l][gatecol][k] col-major fp16: cols 0..511 = r, 512..1023 = z, 1024..1535 = n
// k 0..511 = Wp (S pass), 512..1023 = w_hh (X pass)
__device__ __align__(128) __half g_Bh[2][G3][1024];

// ---------------- helpers ----------------
__device__ __forceinline__ unsigned long long gtimer() {
    unsigned long long t;
    asm volatile("mov.u64 %0, %%globaltimer;" : "=l"(t));
    return t;
}
#define TSB(id) do { if (threadIdx.x == 0) atomicMin(&g_ts[id][0], gtimer()); } while (0)
#define TSE(id) do { if (threadIdx.x == 0) atomicMax(&g_ts[id][1], gtimer()); } while (0)

__device__ __forceinline__ uint32_t f2tf(float f) {
    uint32_t u;
    asm("cvt.rna.tf32.f32 %0, %1;" : "=r"(u) : "f"(f));
    return u;
}
__device__ __forceinline__ float sigm(float v) { return 1.f / (1.f + __expf(-v)); }
__device__ __forceinline__ float tanh_fast(float v) { return 1.f - 2.f / (__expf(2.f * v) + 1.f); }

__device__ __forceinline__ void cpasync16(uint32_t d, const void* s) {
    asm volatile("cp.async.cg.shared.global [%0], [%1], 16;" :: "r"(d), "l"(s));
}
__device__ __forceinline__ void cp_commit() { asm volatile("cp.async.commit_group;"); }
__device__ __forceinline__ void cp_wait1() { asm volatile("cp.async.wait_group 1;" ::: "memory"); }
__device__ __forceinline__ void cp_wait0() { asm volatile("cp.async.wait_group 0;" ::: "memory"); }

__device__ __forceinline__ uint32_t smem_u32(const void* p) {
    uint32_t a;
    asm("{ .reg .u64 t; cvta.to.shared.u64 t, %1; cvt.u32.u64 %0, t; }" : "=r"(a) : "l"(p));
    return a;
}

// fp16 mma, fp32 accum
__device__ __forceinline__ void mma16(float* c, uint32_t a0, uint32_t a1,
                                      uint32_t a2, uint32_t a3,
                                      uint32_t b0, uint32_t b1) {
    asm volatile(
        "mma.sync.aligned.m16n8k16.row.col.f32.f16.f16.f32 "
        "{%0,%1,%2,%3},{%4,%5,%6,%7},{%8,%9},{%0,%1,%2,%3};"
        : "+f"(c[0]), "+f"(c[1]), "+f"(c[2]), "+f"(c[3])
        : "r"(a0), "r"(a1), "r"(a2), "r"(a3), "r"(b0), "r"(b1));
}

// ---------------- timestamp reset / report ----------------
__global__ void k_reset() {
    int i = threadIdx.x;
    if (i < 16) { g_ts[i][0] = ~0ull; g_ts[i][1] = 0; }
}

__global__ void k_report() {
    if (threadIdx.x == 0) {
        unsigned long long base = ~0ull;
        for (int i = 0; i < 13; i++)
            if (g_ts[i][0] < base) base = g_ts[i][0];
        for (int i = 0; i < 13; i++) {
            double st = (double)(g_ts[i][0] - base) / 1000.0;
            double du = (double)(g_ts[i][1] - g_ts[i][0]) / 1000.0;
            printf("TS %2d start=%9.1f dur=%9.1f us\n", i, st, du);
        }
    }
}

// ---------------- dtype detection / prep / CSR ----------------
__global__ void k_detect(const int* __restrict__ A) {
    TSB(0);
    __shared__ int nz;
    if (threadIdx.x == 0) nz = 0;
    __syncthreads();
    if (A[2 * threadIdx.x + 1] != 0) atomicOr(&nz, 1);
    __syncthreads();
    if (threadIdx.x == 0) g_is64 = (nz == 0) ? 1 : 0;
    TSE(0);
}

__global__ void k_prep(const void* __restrict__ Ab, const void* __restrict__ Ib) {
    TSB(1);
    int idx = blockIdx.x * blockDim.x + threadIdx.x;
    int is64 = g_is64;
    if (idx < 2 * NE) {
        long long v = is64 ? ((const long long*)Ab)[idx]
                           : (long long)((const int*)Ab)[idx];
        if (idx < NE) g_src[idx] = (int)v;
        else          g_dst[idx - NE] = (int)v;
    } else if (idx < 2 * NE + NN) {
        int i = idx - 2 * NE;
        long long v = is64 ? ((const long long*)Ib)[i]
                           : (long long)((const int*)Ib)[i];
        g_inp[i] = (int)v;
    } else if (idx < 2 * NE + NN + NN + 1) {
        g_rowptr[idx - 2 * NE - NN] = 0;
    }
    TSE(1);
}

// merged: x0h = fp16(emb[inputs])  AND  g_Bh[*][*][512:1024) = fp16(w_hh)
#define GX_N (NN * 64)
#define WH_N (G3 * (HH / 4))
__global__ void k_gxw(const float* __restrict__ emb, const float* __restrict__ whh) {
    TSB(2);
    int i = blockIdx.x * blockDim.x + threadIdx.x;
    if (i < GX_N) {
        int row = i >> 6, c = i & 63;
        const float4* src = (const float4*)(emb + (size_t)g_inp[row] * HH + c * 8);
        float4 v0 = src[0], v1 = src[1];
        __half2 h0 = __floats2half2_rn(v0.x, v0.y);
        __half2 h1 = __floats2half2_rn(v0.z, v0.w);
        __half2 h2 = __floats2half2_rn(v1.x, v1.y);
        __half2 h3 = __floats2half2_rn(v1.z, v1.w);
        uint4 u;
        u.x = *(uint32_t*)&h0; u.y = *(uint32_t*)&h1;
        u.z = *(uint32_t*)&h2; u.w = *(uint32_t*)&h3;
        *(uint4*)(g_x0h + (size_t)row * HH + c * 8) = u;
    } else {
        int j = i - GX_N;
        if (j < WH_N) {
            int row = j >> 7, c4 = j & 127;
            float4 v = ((const float4*)(whh + (size_t)row * HH))[c4];
            __half2 h0 = __floats2half2_rn(v.x, v.y);
            __half2 h1 = __floats2half2_rn(v.z, v.w);
            uint2 u = make_uint2(*(uint32_t*)&h0, *(uint32_t*)&h1);
            *(uint2*)&g_Bh[0][row][512 + c4 * 4] = u;
            *(uint2*)&g_Bh[1][row][512 + c4 * 4] = u;
        }
    }
    TSE(2);
}

__global__ void k_hist() {
    TSB(3);
    int e = blockIdx.x * blockDim.x + threadIdx.x;
    if (e < NE) atomicAdd(&g_rowptr[g_dst[e] + 1], 1);
    TSE(3);
}

// ---- multi-block scan of g_rowptr[1..NN] ----
__global__ void k_scan1() {  // grid 49, block 1024: per-block inclusive scan
    TSB(4);
    __shared__ int sh[1024];
    int t = threadIdx.x;
    int i = blockIdx.x * 1024 + t;
    int v = (i < NN) ? g_rowptr[i + 1] : 0;
    sh[t] = v;
    __syncthreads();
    for (int off = 1; off < 1024; off <<= 1) {
        int u = (t >= off) ? sh[t - off] : 0;
        __syncthreads();
        sh[t] += u;
        __syncthreads();
    }
    if (i < NN) g_rowptr[i + 1] = sh[t];
    if (t == 1023) g_bsum[blockIdx.x] = sh[1023];
    TSE(4);
}

__global__ void k_scan2() {  // serial scan of 49 block sums (tiny)
    TSB(5);
    if (threadIdx.x == 0) {
        int run = 0;
        for (int b = 0; b < 49; b++) {
            int v = g_bsum[b];
            g_bsum[b] = run;
            run += v;
        }
    }
    TSE(5);
}

__global__ void k_scan3() {  // add block offsets; emit cursor in the same pass
    TSB(6);
    int i = blockIdx.x * 1024 + threadIdx.x;
    if (i < NN) {
        int v = g_rowptr[i + 1] + g_bsum[blockIdx.x];
        g_rowptr[i + 1] = v;
        if (i + 1 < NN) g_cursor[i + 1] = v;
        if (i == 0) g_cursor[0] = 0;
    }
    TSE(6);
}

__global__ void k_fill() {
    TSB(7);
    int e = blockIdx.x * blockDim.x + threadIdx.x;
    if (e < NE) {
        int p = atomicAdd(&g_cursor[g_dst[e]], 1);
        g_csr[p] = g_src[e];
    }
    TSE(7);
}

// S[node] = sum over in-edges of xh[src]; 4 nodes/block, 64 thr/node,
// 4-edge MLP batches (avg degree = 4)
__global__ void __launch_bounds__(256) k_gsum(int xsel) {
    TSB(9 + 2 * xsel);
    const __half* __restrict__ X = xsel ? g_x1h : g_x0h;
    int node = blockIdx.x * 4 + (threadIdx.x >> 6);
    if (node < NN) {
        int t = threadIdx.x & 63;
        int beg = g_rowptr[node], end = g_rowptr[node + 1];
        float a[8];
#pragma unroll
        for (int q = 0; q < 8; q++) a[q] = 0.f;
        int j = beg;
        for (; j + 3 < end; j += 4) {
            int s0 = g_csr[j], s1 = g_csr[j + 1], s2 = g_csr[j + 2], s3 = g_csr[j + 3];
            uint4 u0 = *(const uint4*)(X + (size_t)s0 * HH + t * 8);
            uint4 u1 = *(const uint4*)(X + (size_t)s1 * HH + t * 8);
            uint4 u2 = *(const uint4*)(X + (size_t)s2 * HH + t * 8);
            uint4 u3 = *(const uint4*)(X + (size_t)s3 * HH + t * 8);
#pragma unroll
            for (int q = 0; q < 4; q++) {
                float2 f0 = __half22float2(*((__half2*)&u0 + q));
                float2 f1 = __half22float2(*((__half2*)&u1 + q));
                float2 f2 = __half22float2(*((__half2*)&u2 + q));
                float2 f3 = __half22float2(*((__half2*)&u3 + q));
                a[2 * q]     += (f0.x + f1.x) + (f2.x + f3.x);
                a[2 * q + 1] += (f0.y + f1.y) + (f2.y + f3.y);
            }
        }
        for (; j < end; j++) {
            int s0 = g_csr[j];
            uint4 u0 = *(const uint4*)(X + (size_t)s0 * HH + t * 8);
#pragma unroll
            for (int q = 0; q < 4; q++) {
                float2 f0 = __half22float2(*((__half2*)&u0 + q));
                a[2 * q] += f0.x;
                a[2 * q + 1] += f0.y;
            }
        }
        uint4 o;
        __half2 h0 = __floats2half2_rn(a[0], a[1]);
        __half2 h1 = __floats2half2_rn(a[2], a[3]);
        __half2 h2 = __floats2half2_rn(a[4], a[5]);
        __half2 h3 = __floats2half2_rn(a[6], a[7]);
        o.x = *(uint32_t*)&h0; o.y = *(uint32_t*)&h1;
        o.z = *(uint32_t*)&h2; o.w = *(uint32_t*)&h3;
        *(uint4*)(g_Sh + (size_t)node * HH + t * 8) = o;
    }
    TSE(9 + 2 * xsel);
}

// ---------------- g_Bh k<512 : Wp[l] = W_l @ w_ih^T (tf32 mma, transposed) --
// blockIdx.z = layer
__global__ void __launch_bounds__(256) k_wp(const float* __restrict__ Wbase,
                                            const float* __restrict__ Wih) {
    TSB(8);
    const int layer = blockIdx.z;
    const float* __restrict__ W = Wbase + (size_t)layer * HH * HH;
    __shared__ __align__(16) uint32_t As[64][36];
    __shared__ __align__(16) uint32_t Bs[32][36];
    const int tid = threadIdx.x;
    const int lane = tid & 31, wid = tid >> 5;
    const int wm = wid & 3, wn = wid >> 2;
    const int g8 = lane >> 2, t4 = lane & 3;
    const int i0 = blockIdx.y * 64;   // k index of Wp
    const int c0 = blockIdx.x * 32;   // gate col
    float acc[8];
#pragma unroll
    for (int b = 0; b < 8; b++) acc[b] = 0.f;

    for (int kt = 0; kt < 16; kt++) {
        const int kk0 = kt * 32;
        __syncthreads();
#pragma unroll
        for (int r2 = 0; r2 < 2; r2++) {
            int v = tid + 256 * r2;
            int row = v >> 3, c4 = v & 7;
            float4 a = *(const float4*)(W + (size_t)(i0 + row) * HH + kk0 + c4 * 4);
            uint4 u; u.x = f2tf(a.x); u.y = f2tf(a.y); u.z = f2tf(a.z); u.w = f2tf(a.w);
            *(uint4*)&As[row][c4 * 4] = u;
        }
        {
            int col = tid >> 3, k4 = tid & 7;
            float4 b = *(const float4*)(Wih + (size_t)(c0 + col) * HH + kk0 + k4 * 4);
            uint4 u; u.x = f2tf(b.x); u.y = f2tf(b.y); u.z = f2tf(b.z); u.w = f2tf(b.w);
            *(uint4*)&Bs[col][k4 * 4] = u;
        }
        __syncthreads();
#pragma unroll
        for (int ks = 0; ks < 4; ks++) {
            const int kb = ks * 8;
            uint32_t a0 = As[wm * 16 + g8][kb + t4];
            uint32_t a1 = As[wm * 16 + g8 + 8][kb + t4];
            uint32_t a2 = As[wm * 16 + g8][kb + t4 + 4];
            uint32_t a3 = As[wm * 16 + g8 + 8][kb + t4 + 4];
#pragma unroll
            for (int nt = 0; nt < 2; nt++) {
                int nc = wn * 16 + nt * 8 + g8;
                uint32_t b0 = Bs[nc][kb + t4];
                uint32_t b1 = Bs[nc][kb + t4 + 4];
                asm volatile(
                    "mma.sync.aligned.m16n8k8.row.col.f32.tf32.tf32.f32 "
                    "{%0,%1,%2,%3},{%4,%5,%6,%7},{%8,%9},{%0,%1,%2,%3};"
                    : "+f"(acc[nt * 4 + 0]), "+f"(acc[nt * 4 + 1]),
                      "+f"(acc[nt * 4 + 2]), "+f"(acc[nt * 4 + 3])
                    : "r"(a0), "r"(a1), "r"(a2), "r"(a3), "r"(b0), "r"(b1));
            }
        }
    }
#pragma unroll
    for (int nt = 0; nt < 2; nt++)
#pragma unroll
        for (int j = 0; j < 4; j++) {
            int krow = i0 + wm * 16 + g8 + ((j >> 1) << 3);
            int col = c0 + wn * 16 + nt * 8 + t4 * 2 + (j & 1);
            g_Bh[layer][col][krow] = __float2half_rn(acc[nt * 4 + j]);
        }
    TSE(8);
}

// ---------------- fused fp16 GEMM + GRU, merged K=1024, 3-stage pipeline ----
// Block tile: 64 m x 64 n-cols, 256 threads, 2 CTAs/SM (epilogue overlap).
// 8 warps: wm=wid&1 (m32), wn=wid>>1 (n16). k-tile = 64 halves, 16 tiles.
#define STRIDE_H 72                       // halves per smem row (64 + 8 pad)
#define ST_A (64 * STRIDE_H * 2)          // 9216 B
#define ST_B (192 * STRIDE_H * 2)         // 27648 B
#define ST_SZ (ST_A + ST_B)               // 36864 B
#define N_STAGE 3
#define SM_TOTAL (N_STAGE * ST_SZ)        // 110592 B

__global__ void __launch_bounds__(256, 2) k_fused(int layer, int xsel, int final_out,
                                                  float* __restrict__ dout,
                                                  const float* __restrict__ bih,
                                                  const float* __restrict__ bhh) {
    TSB(10 + 2 * layer);
    extern __shared__ __align__(16) char smem[];
    const uint32_t sbase = smem_u32(smem);

    const __half* __restrict__ Xh = xsel ? g_x1h : g_x0h;   // also the h-state
    const __half* __restrict__ Bh = &g_Bh[layer][0][0];

    const int tid = threadIdx.x;
    const int lane = tid & 31, wid = tid >> 5;
    const int wm = wid & 1, wn = wid >> 1;
    const int g8 = lane >> 2, t4 = lane & 3;
    const int i0 = blockIdx.y * 64;
    const int c0 = blockIdx.x * 64;

    float accR[2][2][4], accZ[2][2][4], accN1[2][2][4], accN2[2][2][4];
#pragma unroll
    for (int mf = 0; mf < 2; mf++)
#pragma unroll
        for (int nf = 0; nf < 2; nf++)
#pragma unroll
            for (int j = 0; j < 4; j++) {
                accR[mf][nf][j] = 0.f; accZ[mf][nf][j] = 0.f;
                accN1[mf][nf][j] = 0.f; accN2[mf][nf][j] = 0.f;
            }

    // ---- async tile loader: tile t in 0..15, pass = t>>3, kt = t&7 ----
    auto load_tile = [&](int s, int t) {
        const int pass = t >> 3;
        const int k0 = (t & 7) * 64;   // halves within the 512-half row
        const __half* Ap = pass ? Xh : g_Sh;
        const uint32_t sA = sbase + s * ST_SZ;
        const uint32_t sB = sA + ST_A;
#pragma unroll
        for (int i = 0; i < 2; i++) {   // A: 64 rows x 8 chunks of 16B
            int v = tid + 256 * i;
            int row = v >> 3, c = v & 7;
            int gr = i0 + row;
            if (gr >= NN) gr = NN - 1;  // dup rows discarded in epilogue
            const __half* src = Ap + (size_t)gr * HH + k0 + c * 8;
            cpasync16(sA + (uint32_t)(row * (STRIDE_H * 2) + c * 16), src);
        }
#pragma unroll
        for (int i = 0; i < 6; i++) {   // B: 192 cols x 8 chunks of 16B
            int v = tid + 256 * i;
            int col = v >> 3, c = v & 7;
            int gate = col >> 6, j = col & 63;
            const __half* src = Bh + (size_t)(gate * 512 + c0 + j) * 1024 +
                                pass * 512 + k0 + c * 8;
            cpasync16(sB + (uint32_t)(col * (STRIDE_H * 2) + c * 16), src);
        }
    };

    load_tile(0, 0);
    cp_commit();
    load_tile(1, 1);
    cp_commit();

    for (int t = 0; t < 16; t++) {
        if (t < 15) cp_wait1();   // tile t landed; t+1 still in flight
        else        cp_wait0();
        __syncthreads();          // all warps done with tile t-1's stage
        if (t + 2 < 16) {         // prefetch into stage (t+2)%3 (= stage of t-1)
            load_tile((t + 2) % N_STAGE, t + 2);
            cp_commit();
        }
        const int pass = t >> 3;
        const char* stg = smem + (t % N_STAGE) * ST_SZ;
        const __half* As = (const __half*)stg;
        const __half* Bs = (const __half*)(stg + ST_A);
#pragma unroll
        for (int ks = 0; ks < 4; ks++) {
            const int kb = ks * 16;
            uint32_t a[2][4];
#pragma unroll
            for (int mf = 0; mf < 2; mf++) {
                const __half* pa = As + (wm * 32 + mf * 16 + g8) * STRIDE_H + kb + 2 * t4;
                a[mf][0] = *(const uint32_t*)(pa);
                a[mf][1] = *(const uint32_t*)(pa + 8 * STRIDE_H);
                a[mf][2] = *(const uint32_t*)(pa + 8);
                a[mf][3] = *(const uint32_t*)(pa + 8 * STRIDE_H + 8);
            }
#pragma unroll
            for (int g = 0; g < 3; g++) {
#pragma unroll
                for (int nf = 0; nf < 2; nf++) {
                    int nc = wn * 16 + nf * 8 + g8;
                    const __half* pb = Bs + (g * 64 + nc) * STRIDE_H + kb + 2 * t4;
                    uint32_t b0 = *(const uint32_t*)(pb);
                    uint32_t b1 = *(const uint32_t*)(pb + 8);
#pragma unroll
                    for (int mf = 0; mf < 2; mf++) {
                        float* dst = (g == 0) ? accR[mf][nf]
                                   : (g == 1) ? accZ[mf][nf]
                                   : (pass == 0) ? accN1[mf][nf] : accN2[mf][nf];
                        mma16(dst, a[mf][0], a[mf][1], a[mf][2], a[mf][3], b0, b1);
                    }
                }
            }
        }
    }

    // ---- GRU epilogue: h from fp16 Xh (sequential rows) ----
#pragma unroll
    for (int mf = 0; mf < 2; mf++)
#pragma unroll
        for (int nf = 0; nf < 2; nf++) {
            const int colb = c0 + wn * 16 + nf * 8 + t4 * 2;
#pragma unroll
            for (int half_ = 0; half_ < 2; half_++) {   // j pair: rows g8 / g8+8
                int row = i0 + wm * 32 + mf * 16 + g8 + half_ * 8;
                if (row < NN) {
                    uint32_t hu = *(const uint32_t*)(Xh + (size_t)row * HH + colb);
                    float2 hv = __half22float2(*(__half2*)&hu);
                    float o[2];
#pragma unroll
                    for (int q = 0; q < 2; q++) {
                        int j = half_ * 2 + q;
                        int cl = colb + q;
                        float vr = accR[mf][nf][j] + __ldg(bih + cl) + __ldg(bhh + cl);
                        float vz = accZ[mf][nf][j] + __ldg(bih + cl + HH) + __ldg(bhh + cl + HH);
                        float r = sigm(vr);
                        float z = sigm(vz);
                        float n = tanh_fast(accN1[mf][nf][j] + __ldg(bih + cl + 2 * HH) +
                                            r * (accN2[mf][nf][j] + __ldg(bhh + cl + 2 * HH)));
                        float h = (q == 0) ? hv.x : hv.y;
                        o[q] = (1.f - z) * n + z * h;
                    }
                    if (final_out) {
                        *(float2*)(dout + (size_t)row * HH + colb) = make_float2(o[0], o[1]);
                    } else {
                        __half2 hh = __floats2half2_rn(o[0], o[1]);
                        *(uint32_t*)(g_x1h + (size_t)row * HH + colb) = *(uint32_t*)&hh;
                    }
                }
            }
        }
    TSE(10 + 2 * layer);
}

// ---------------- launch ----------------
extern "C" void kernel_launch(void* const* d_in, const int* in_sizes, int n_in,
                              void* d_out, int out_size) {
    const void* inputs = d_in[0];
    const void* A      = d_in[1];
    const float* emb    = (const float*)d_in[2];
    const float* weight = (const float*)d_in[3];
    const float* w_ih   = (const float*)d_in[4];
    const float* w_hh   = (const float*)d_in[5];
    const float* b_ih   = (const float*)d_in[6];
    const float* b_hh   = (const float*)d_in[7];
    float* out = (float*)d_out;

    cudaFuncSetAttribute(k_fused, cudaFuncAttributeMaxDynamicSharedMemorySize, SM_TOTAL);

    k_reset<<<1, 16>>>();
    k_detect<<<1, 128>>>((const int*)A);
    int T = 2 * NE + NN + NN + 1;
    k_prep<<<(T + 255) / 256, 256>>>(A, inputs);
    k_gxw<<<(GX_N + WH_N + 255) / 256, 256>>>(emb, w_hh);
    k_hist<<<(NE + 255) / 256, 256>>>();
    k_scan1<<<49, 1024>>>();
    k_scan2<<<1, 32>>>();
    k_scan3<<<49, 1024>>>();
    k_fill<<<(NE + 255) / 256, 256>>>();
    k_wp<<<dim3(G3 / 32, HH / 64, 2), 256>>>(weight, w_ih);
    k_gsum<<<(NN + 3) / 4, 256>>>(0);
    k_fused<<<dim3(HH / 64, (NN + 63) / 64), 256, SM_TOTAL>>>(
        0, 0, 0, out, b_ih, b_hh);
    k_gsum<<<(NN + 3) / 4, 256>>>(1);
    k_fused<<<dim3(HH / 64, (NN + 63) / 64), 256, SM_TOTAL>>>(
        1, 1, 1, out, b_ih, b_hh);
    k_report<<<1, 32>>>();
}

// round 14
// speedup vs baseline: 1.1200x; 1.1200x over previous
#include <cuda_runtime.h>
#include <cuda_fp16.h>
#include <cstdint>

#define NN 50000
#define NE 200000
#define HH 512
#define G3 1536

// ---------------- device scratch (static, no allocation) ----------------
__device__ int g_is64;
__device__ int g_src[NE];
__device__ int g_dst[NE];
__device__ int g_inp[NN];
__device__ int g_rowptr[NN + 1];
__device__ int g_cursor[NN];
__device__ int g_csr[NE];
__device__ int g_bsum[64];
__device__ __align__(128) __half g_x0h[(size_t)NN * HH]; // fp16 node states
__device__ __align__(128) __half g_x1h[(size_t)NN * HH];
__device__ __align__(128) __half g_Sh[(size_t)NN * HH];
// g_Bh[l][gatecol][k] col-major fp16: cols 0..511 = r, 512..1023 = z, 1024..1535 = n
// k 0..511 = Wp (S pass), 512..1023 = w_hh (X pass)
__device__ __align__(128) __half g_Bh[2][G3][1024];

// ---------------- helpers ----------------
__device__ __forceinline__ uint32_t f2tf(float f) {
    uint32_t u;
    asm("cvt.rna.tf32.f32 %0, %1;" : "=r"(u) : "f"(f));
    return u;
}
__device__ __forceinline__ float sigm(float v) { return 1.f / (1.f + __expf(-v)); }
__device__ __forceinline__ float tanh_fast(float v) { return 1.f - 2.f / (__expf(2.f * v) + 1.f); }

__device__ __forceinline__ void cpasync16(uint32_t d, const void* s) {
    asm volatile("cp.async.cg.shared.global [%0], [%1], 16;" :: "r"(d), "l"(s));
}
__device__ __forceinline__ void cp_commit() { asm volatile("cp.async.commit_group;"); }
__device__ __forceinline__ void cp_wait1() { asm volatile("cp.async.wait_group 1;" ::: "memory"); }
__device__ __forceinline__ void cp_wait0() { asm volatile("cp.async.wait_group 0;" ::: "memory"); }

__device__ __forceinline__ uint32_t smem_u32(const void* p) {
    uint32_t a;
    asm("{ .reg .u64 t; cvta.to.shared.u64 t, %1; cvt.u32.u64 %0, t; }" : "=r"(a) : "l"(p));
    return a;
}

// fp16 mma, fp32 accum
__device__ __forceinline__ void mma16(float* c, uint32_t a0, uint32_t a1,
                                      uint32_t a2, uint32_t a3,
                                      uint32_t b0, uint32_t b1) {
    asm volatile(
        "mma.sync.aligned.m16n8k16.row.col.f32.f16.f16.f32 "
        "{%0,%1,%2,%3},{%4,%5,%6,%7},{%8,%9},{%0,%1,%2,%3};"
        : "+f"(c[0]), "+f"(c[1]), "+f"(c[2]), "+f"(c[3])
        : "r"(a0), "r"(a1), "r"(a2), "r"(a3), "r"(b0), "r"(b1));
}

// ---------------- dtype detection / prep / CSR ----------------
__global__ void k_detect(const int* __restrict__ A) {
    __shared__ int nz;
    if (threadIdx.x == 0) nz = 0;
    __syncthreads();
    if (A[2 * threadIdx.x + 1] != 0) atomicOr(&nz, 1);
    __syncthreads();
    if (threadIdx.x == 0) g_is64 = (nz == 0) ? 1 : 0;
}

__global__ void k_prep(const void* __restrict__ Ab, const void* __restrict__ Ib) {
    int idx = blockIdx.x * blockDim.x + threadIdx.x;
    int is64 = g_is64;
    if (idx < 2 * NE) {
        long long v = is64 ? ((const long long*)Ab)[idx]
                           : (long long)((const int*)Ab)[idx];
        if (idx < NE) g_src[idx] = (int)v;
        else          g_dst[idx - NE] = (int)v;
    } else if (idx < 2 * NE + NN) {
        int i = idx - 2 * NE;
        long long v = is64 ? ((const long long*)Ib)[i]
                           : (long long)((const int*)Ib)[i];
        g_inp[i] = (int)v;
    } else if (idx < 2 * NE + NN + NN + 1) {
        g_rowptr[idx - 2 * NE - NN] = 0;
    }
}

// merged: x0h = fp16(emb[inputs])  AND  g_Bh[*][*][512:1024) = fp16(w_hh)
#define GX_N (NN * 64)
#define WH_N (G3 * (HH / 4))
__global__ void k_gxw(const float* __restrict__ emb, const float* __restrict__ whh) {
    int i = blockIdx.x * blockDim.x + threadIdx.x;
    if (i < GX_N) {
        int row = i >> 6, c = i & 63;
        const float4* src = (const float4*)(emb + (size_t)g_inp[row] * HH + c * 8);
        float4 v0 = src[0], v1 = src[1];
        __half2 h0 = __floats2half2_rn(v0.x, v0.y);
        __half2 h1 = __floats2half2_rn(v0.z, v0.w);
        __half2 h2 = __floats2half2_rn(v1.x, v1.y);
        __half2 h3 = __floats2half2_rn(v1.z, v1.w);
        uint4 u;
        u.x = *(uint32_t*)&h0; u.y = *(uint32_t*)&h1;
        u.z = *(uint32_t*)&h2; u.w = *(uint32_t*)&h3;
        *(uint4*)(g_x0h + (size_t)row * HH + c * 8) = u;
    } else {
        int j = i - GX_N;
        if (j < WH_N) {
            int row = j >> 7, c4 = j & 127;
            float4 v = ((const float4*)(whh + (size_t)row * HH))[c4];
            __half2 h0 = __floats2half2_rn(v.x, v.y);
            __half2 h1 = __floats2half2_rn(v.z, v.w);
            uint2 u = make_uint2(*(uint32_t*)&h0, *(uint32_t*)&h1);
            *(uint2*)&g_Bh[0][row][512 + c4 * 4] = u;
            *(uint2*)&g_Bh[1][row][512 + c4 * 4] = u;
        }
    }
}

__global__ void k_hist() {
    int e = blockIdx.x * blockDim.x + threadIdx.x;
    if (e < NE) atomicAdd(&g_rowptr[g_dst[e] + 1], 1);
}

// ---- multi-block scan of g_rowptr[1..NN] ----
__global__ void k_scan1() {  // grid 49, block 1024: per-block inclusive scan
    __shared__ int sh[1024];
    int t = threadIdx.x;
    int i = blockIdx.x * 1024 + t;
    int v = (i < NN) ? g_rowptr[i + 1] : 0;
    sh[t] = v;
    __syncthreads();
    for (int off = 1; off < 1024; off <<= 1) {
        int u = (t >= off) ? sh[t - off] : 0;
        __syncthreads();
        sh[t] += u;
        __syncthreads();
    }
    if (i < NN) g_rowptr[i + 1] = sh[t];
    if (t == 1023) g_bsum[blockIdx.x] = sh[1023];
}

__global__ void k_scan2() {  // serial scan of 49 block sums (tiny)
    if (threadIdx.x == 0) {
        int run = 0;
        for (int b = 0; b < 49; b++) {
            int v = g_bsum[b];
            g_bsum[b] = run;
            run += v;
        }
    }
}

__global__ void k_scan3() {  // add block offsets; emit cursor in the same pass
    int i = blockIdx.x * 1024 + threadIdx.x;
    if (i < NN) {
        int v = g_rowptr[i + 1] + g_bsum[blockIdx.x];
        g_rowptr[i + 1] = v;
        if (i + 1 < NN) g_cursor[i + 1] = v;
        if (i == 0) g_cursor[0] = 0;
    }
}

__global__ void k_fill() {
    int e = blockIdx.x * blockDim.x + threadIdx.x;
    if (e < NE) {
        int p = atomicAdd(&g_cursor[g_dst[e]], 1);
        g_csr[p] = g_src[e];
    }
}

// S[node] = sum over in-edges of xh[src]; 4 nodes/block, 64 thr/node,
// 4-edge MLP batches (avg degree = 4)
__global__ void __launch_bounds__(256) k_gsum(int xsel) {
    const __half* __restrict__ X = xsel ? g_x1h : g_x0h;
    int node = blockIdx.x * 4 + (threadIdx.x >> 6);
    if (node >= NN) return;
    int t = threadIdx.x & 63;
    int beg = g_rowptr[node], end = g_rowptr[node + 1];
    float a[8];
#pragma unroll
    for (int q = 0; q < 8; q++) a[q] = 0.f;
    int j = beg;
    for (; j + 3 < end; j += 4) {
        int s0 = g_csr[j], s1 = g_csr[j + 1], s2 = g_csr[j + 2], s3 = g_csr[j + 3];
        uint4 u0 = *(const uint4*)(X + (size_t)s0 * HH + t * 8);
        uint4 u1 = *(const uint4*)(X + (size_t)s1 * HH + t * 8);
        uint4 u2 = *(const uint4*)(X + (size_t)s2 * HH + t * 8);
        uint4 u3 = *(const uint4*)(X + (size_t)s3 * HH + t * 8);
#pragma unroll
        for (int q = 0; q < 4; q++) {
            float2 f0 = __half22float2(*((__half2*)&u0 + q));
            float2 f1 = __half22float2(*((__half2*)&u1 + q));
            float2 f2 = __half22float2(*((__half2*)&u2 + q));
            float2 f3 = __half22float2(*((__half2*)&u3 + q));
            a[2 * q]     += (f0.x + f1.x) + (f2.x + f3.x);
            a[2 * q + 1] += (f0.y + f1.y) + (f2.y + f3.y);
        }
    }
    for (; j < end; j++) {
        int s0 = g_csr[j];
        uint4 u0 = *(const uint4*)(X + (size_t)s0 * HH + t * 8);
#pragma unroll
        for (int q = 0; q < 4; q++) {
            float2 f0 = __half22float2(*((__half2*)&u0 + q));
            a[2 * q] += f0.x;
            a[2 * q + 1] += f0.y;
        }
    }
    uint4 o;
    __half2 h0 = __floats2half2_rn(a[0], a[1]);
    __half2 h1 = __floats2half2_rn(a[2], a[3]);
    __half2 h2 = __floats2half2_rn(a[4], a[5]);
    __half2 h3 = __floats2half2_rn(a[6], a[7]);
    o.x = *(uint32_t*)&h0; o.y = *(uint32_t*)&h1;
    o.z = *(uint32_t*)&h2; o.w = *(uint32_t*)&h3;
    *(uint4*)(g_Sh + (size_t)node * HH + t * 8) = o;
}

// ---------------- g_Bh k<512 : Wp[l] = W_l @ w_ih^T (tf32 mma, transposed) --
// blockIdx.z = layer
__global__ void __launch_bounds__(256) k_wp(const float* __restrict__ Wbase,
                                            const float* __restrict__ Wih) {
    const int layer = blockIdx.z;
    const float* __restrict__ W = Wbase + (size_t)layer * HH * HH;
    __shared__ __align__(16) uint32_t As[64][36];
    __shared__ __align__(16) uint32_t Bs[32][36];
    const int tid = threadIdx.x;
    const int lane = tid & 31, wid = tid >> 5;
    const int wm = wid & 3, wn = wid >> 2;
    const int g8 = lane >> 2, t4 = lane & 3;
    const int i0 = blockIdx.y * 64;   // k index of Wp
    const int c0 = blockIdx.x * 32;   // gate col
    float acc[8];
#pragma unroll
    for (int b = 0; b < 8; b++) acc[b] = 0.f;

    for (int kt = 0; kt < 16; kt++) {
        const int kk0 = kt * 32;
        __syncthreads();
#pragma unroll
        for (int r2 = 0; r2 < 2; r2++) {
            int v = tid + 256 * r2;
            int row = v >> 3, c4 = v & 7;
            float4 a = *(const float4*)(W + (size_t)(i0 + row) * HH + kk0 + c4 * 4);
            uint4 u; u.x = f2tf(a.x); u.y = f2tf(a.y); u.z = f2tf(a.z); u.w = f2tf(a.w);
            *(uint4*)&As[row][c4 * 4] = u;
        }
        {
            int col = tid >> 3, k4 = tid & 7;
            float4 b = *(const float4*)(Wih + (size_t)(c0 + col) * HH + kk0 + k4 * 4);
            uint4 u; u.x = f2tf(b.x); u.y = f2tf(b.y); u.z = f2tf(b.z); u.w = f2tf(b.w);
            *(uint4*)&Bs[col][k4 * 4] = u;
        }
        __syncthreads();
#pragma unroll
        for (int ks = 0; ks < 4; ks++) {
            const int kb = ks * 8;
            uint32_t a0 = As[wm * 16 + g8][kb + t4];
            uint32_t a1 = As[wm * 16 + g8 + 8][kb + t4];
            uint32_t a2 = As[wm * 16 + g8][kb + t4 + 4];
            uint32_t a3 = As[wm * 16 + g8 + 8][kb + t4 + 4];
#pragma unroll
            for (int nt = 0; nt < 2; nt++) {
                int nc = wn * 16 + nt * 8 + g8;
                uint32_t b0 = Bs[nc][kb + t4];
                uint32_t b1 = Bs[nc][kb + t4 + 4];
                asm volatile(
                    "mma.sync.aligned.m16n8k8.row.col.f32.tf32.tf32.f32 "
                    "{%0,%1,%2,%3},{%4,%5,%6,%7},{%8,%9},{%0,%1,%2,%3};"
                    : "+f"(acc[nt * 4 + 0]), "+f"(acc[nt * 4 + 1]),
                      "+f"(acc[nt * 4 + 2]), "+f"(acc[nt * 4 + 3])
                    : "r"(a0), "r"(a1), "r"(a2), "r"(a3), "r"(b0), "r"(b1));
            }
        }
    }
#pragma unroll
    for (int nt = 0; nt < 2; nt++)
#pragma unroll
        for (int j = 0; j < 4; j++) {
            int krow = i0 + wm * 16 + g8 + ((j >> 1) << 3);
            int col = c0 + wn * 16 + nt * 8 + t4 * 2 + (j & 1);
            g_Bh[layer][col][krow] = __float2half_rn(acc[nt * 4 + j]);
        }
}

// ---------------- fused fp16 GEMM + GRU, merged K=1024, 3-stage pipeline ----
// Block tile: 128 m x 64 n-cols. 16 warps: wm=wid&3 (m32), wn=wid>>2 (n16).
// k-tile = 64 halves. 16 tiles (8 S-pass + 8 X-pass).
#define STRIDE_H 72                       // halves per smem row (64 + 8 pad)
#define ST_A (128 * STRIDE_H * 2)         // 18432 B
#define ST_B (192 * STRIDE_H * 2)         // 27648 B
#define ST_SZ (ST_A + ST_B)               // 46080 B
#define N_STAGE 3
#define SM_TOTAL (N_STAGE * ST_SZ)        // 138240 B

__global__ void __launch_bounds__(512, 1) k_fused(int layer, int xsel, int final_out,
                                                  float* __restrict__ dout,
                                                  const float* __restrict__ bih,
                                                  const float* __restrict__ bhh) {
    extern __shared__ __align__(16) char smem[];
    const uint32_t sbase = smem_u32(smem);

    const __half* __restrict__ Xh = xsel ? g_x1h : g_x0h;   // also the h-state
    const __half* __restrict__ Bh = &g_Bh[layer][0][0];

    const int tid = threadIdx.x;
    const int lane = tid & 31, wid = tid >> 5;
    const int wm = wid & 3, wn = wid >> 2;
    const int g8 = lane >> 2, t4 = lane & 3;
    const int i0 = blockIdx.y * 128;
    const int c0 = blockIdx.x * 64;

    // ---- prefetch epilogue h-values (independent of GEMM; hides latency) ----
    uint32_t hpre[2][2][2];
#pragma unroll
    for (int mf = 0; mf < 2; mf++)
#pragma unroll
        for (int nf = 0; nf < 2; nf++) {
            const int colb = c0 + wn * 16 + nf * 8 + t4 * 2;
#pragma unroll
            for (int half_ = 0; half_ < 2; half_++) {
                int row = i0 + wm * 32 + mf * 16 + g8 + half_ * 8;
                hpre[mf][nf][half_] = (row < NN)
                    ? *(const uint32_t*)(Xh + (size_t)row * HH + colb) : 0u;
            }
        }

    float accR[2][2][4], accZ[2][2][4], accN1[2][2][4], accN2[2][2][4];
#pragma unroll
    for (int mf = 0; mf < 2; mf++)
#pragma unroll
        for (int nf = 0; nf < 2; nf++)
#pragma unroll
            for (int j = 0; j < 4; j++) {
                accR[mf][nf][j] = 0.f; accZ[mf][nf][j] = 0.f;
                accN1[mf][nf][j] = 0.f; accN2[mf][nf][j] = 0.f;
            }

    // ---- async tile loader: tile t in 0..15, pass = t>>3, kt = t&7 ----
    auto load_tile = [&](int s, int t) {
        const int pass = t >> 3;
        const int k0 = (t & 7) * 64;   // halves within the 512-half row
        const __half* Ap = pass ? Xh : g_Sh;
        const uint32_t sA = sbase + s * ST_SZ;
        const uint32_t sB = sA + ST_A;
#pragma unroll
        for (int i = 0; i < 2; i++) {   // A: 128 rows x 8 chunks of 16B
            int v = tid + 512 * i;
            int row = v >> 3, c = v & 7;
            int gr = i0 + row;
            if (gr >= NN) gr = NN - 1;  // dup rows discarded in epilogue
            const __half* src = Ap + (size_t)gr * HH + k0 + c * 8;
            cpasync16(sA + (uint32_t)(row * (STRIDE_H * 2) + c * 16), src);
        }
#pragma unroll
        for (int i = 0; i < 3; i++) {   // B: 192 cols x 8 chunks of 16B
            int v = tid + 512 * i;
            int col = v >> 3, c = v & 7;
            int gate = col >> 6, j = col & 63;
            const __half* src = Bh + (size_t)(gate * 512 + c0 + j) * 1024 +
                                pass * 512 + k0 + c * 8;
            cpasync16(sB + (uint32_t)(col * (STRIDE_H * 2) + c * 16), src);
        }
    };

    load_tile(0, 0);
    cp_commit();
    load_tile(1, 1);
    cp_commit();

    for (int t = 0; t < 16; t++) {
        if (t < 15) cp_wait1();   // tile t landed; t+1 still in flight
        else        cp_wait0();
        __syncthreads();          // all warps done with tile t-1's stage
        if (t + 2 < 16) {         // prefetch into stage (t+2)%3 (= stage of t-1)
            load_tile((t + 2) % N_STAGE, t + 2);
            cp_commit();
        }
        const int pass = t >> 3;
        const char* stg = smem + (t % N_STAGE) * ST_SZ;
        const __half* As = (const __half*)stg;
        const __half* Bs = (const __half*)(stg + ST_A);
#pragma unroll
        for (int ks = 0; ks < 4; ks++) {
            const int kb = ks * 16;
            uint32_t a[2][4];
#pragma unroll
            for (int mf = 0; mf < 2; mf++) {
                const __half* pa = As + (wm * 32 + mf * 16 + g8) * STRIDE_H + kb + 2 * t4;
                a[mf][0] = *(const uint32_t*)(pa);
                a[mf][1] = *(const uint32_t*)(pa + 8 * STRIDE_H);
                a[mf][2] = *(const uint32_t*)(pa + 8);
                a[mf][3] = *(const uint32_t*)(pa + 8 * STRIDE_H + 8);
            }
#pragma unroll
            for (int g = 0; g < 3; g++) {
#pragma unroll
                for (int nf = 0; nf < 2; nf++) {
                    int nc = wn * 16 + nf * 8 + g8;
                    const __half* pb = Bs + (g * 64 + nc) * STRIDE_H + kb + 2 * t4;
                    uint32_t b0 = *(const uint32_t*)(pb);
                    uint32_t b1 = *(const uint32_t*)(pb + 8);
#pragma unroll
                    for (int mf = 0; mf < 2; mf++) {
                        float* dst = (g == 0) ? accR[mf][nf]
                                   : (g == 1) ? accZ[mf][nf]
                                   : (pass == 0) ? accN1[mf][nf] : accN2[mf][nf];
                        mma16(dst, a[mf][0], a[mf][1], a[mf][2], a[mf][3], b0, b1);
                    }
                }
            }
        }
    }

    // ---- GRU epilogue: h from prefetched registers ----
#pragma unroll
    for (int mf = 0; mf < 2; mf++)
#pragma unroll
        for (int nf = 0; nf < 2; nf++) {
            const int colb = c0 + wn * 16 + nf * 8 + t4 * 2;
#pragma unroll
            for (int half_ = 0; half_ < 2; half_++) {   // j pair: rows g8 / g8+8
                int row = i0 + wm * 32 + mf * 16 + g8 + half_ * 8;
                if (row < NN) {
                    uint32_t hu = hpre[mf][nf][half_];
                    float2 hv = __half22float2(*(__half2*)&hu);
                    float o[2];
#pragma unroll
                    for (int q = 0; q < 2; q++) {
                        int j = half_ * 2 + q;
                        int cl = colb + q;
                        float vr = accR[mf][nf][j] + __ldg(bih + cl) + __ldg(bhh + cl);
                        float vz = accZ[mf][nf][j] + __ldg(bih + cl + HH) + __ldg(bhh + cl + HH);
                        float r = sigm(vr);
                        float z = sigm(vz);
                        float n = tanh_fast(accN1[mf][nf][j] + __ldg(bih + cl + 2 * HH) +
                                            r * (accN2[mf][nf][j] + __ldg(bhh + cl + 2 * HH)));
                        float h = (q == 0) ? hv.x : hv.y;
                        o[q] = (1.f - z) * n + z * h;
                    }
                    if (final_out) {
                        *(float2*)(dout + (size_t)row * HH + colb) = make_float2(o[0], o[1]);
                    } else {
                        __half2 hh = __floats2half2_rn(o[0], o[1]);
                        *(uint32_t*)(g_x1h + (size_t)row * HH + colb) = *(uint32_t*)&hh;
                    }
                }
            }
        }
}

// ---------------- launch ----------------
extern "C" void kernel_launch(void* const* d_in, const int* in_sizes, int n_in,
                              void* d_out, int out_size) {
    const void* inputs = d_in[0];
    const void* A      = d_in[1];
    const float* emb    = (const float*)d_in[2];
    const float* weight = (const float*)d_in[3];
    const float* w_ih   = (const float*)d_in[4];
    const float* w_hh   = (const float*)d_in[5];
    const float* b_ih   = (const float*)d_in[6];
    const float* b_hh   = (const float*)d_in[7];
    float* out = (float*)d_out;

    cudaFuncSetAttribute(k_fused, cudaFuncAttributeMaxDynamicSharedMemorySize, SM_TOTAL);

    k_detect<<<1, 128>>>((const int*)A);
    int T = 2 * NE + NN + NN + 1;
    k_prep<<<(T + 255) / 256, 256>>>(A, inputs);
    k_gxw<<<(GX_N + WH_N + 255) / 256, 256>>>(emb, w_hh);
    k_hist<<<(NE + 255) / 256, 256>>>();
    k_scan1<<<49, 1024>>>();
    k_scan2<<<1, 32>>>();
    k_scan3<<<49, 1024>>>();
    k_fill<<<(NE + 255) / 256, 256>>>();
    k_wp<<<dim3(G3 / 32, HH / 64, 2), 256>>>(weight, w_ih);
    k_gsum<<<(NN + 3) / 4, 256>>>(0);
    k_fused<<<dim3(HH / 64, (NN + 127) / 128), 512, SM_TOTAL>>>(
        0, 0, 0, out, b_ih, b_hh);
    k_gsum<<<(NN + 3) / 4, 256>>>(1);
    k_fused<<<dim3(HH / 64, (NN + 127) / 128), 512, SM_TOTAL>>>(
        1, 1, 1, out, b_ih, b_hh);
}

// round 15
// speedup vs baseline: 1.1739x; 1.0482x over previous
#include <cuda_runtime.h>
#include <cuda_fp16.h>
#include <cstdint>

#define NN 50000
#define NE 200000
#define HH 512
#define G3 1536

// ---------------- device scratch (static, no allocation) ----------------
__device__ int g_is64;
__device__ int g_src[NE];
__device__ int g_dst[NE];
__device__ int g_inp[NN];
__device__ int g_rowptr[NN + 1];
__device__ int g_cursor[NN];
__device__ int g_csr[NE];
__device__ int g_bsum[64];
__device__ __align__(16) float g_bias4[HH][4];           // {br, bz, b_in, b_hn}
__device__ __align__(128) __half g_x0h[(size_t)NN * HH]; // fp16 node states
__device__ __align__(128) __half g_x1h[(size_t)NN * HH];
__device__ __align__(128) __half g_Sh[(size_t)NN * HH];
// g_Bh[l][gatecol][k] col-major fp16: cols 0..511 = r, 512..1023 = z, 1024..1535 = n
// k 0..511 = Wp (S pass), 512..1023 = w_hh (X pass)
__device__ __align__(128) __half g_Bh[2][G3][1024];

// ---------------- helpers ----------------
__device__ __forceinline__ uint32_t f2tf(float f) {
    uint32_t u;
    asm("cvt.rna.tf32.f32 %0, %1;" : "=r"(u) : "f"(f));
    return u;
}
__device__ __forceinline__ float sigm(float v) { return 1.f / (1.f + __expf(-v)); }
__device__ __forceinline__ float tanh_fast(float v) { return 1.f - 2.f / (__expf(2.f * v) + 1.f); }

__device__ __forceinline__ void cpasync16(uint32_t d, const void* s) {
    asm volatile("cp.async.cg.shared.global [%0], [%1], 16;" :: "r"(d), "l"(s));
}
__device__ __forceinline__ void cp_commit() { asm volatile("cp.async.commit_group;"); }
__device__ __forceinline__ void cp_wait1() { asm volatile("cp.async.wait_group 1;" ::: "memory"); }
__device__ __forceinline__ void cp_wait0() { asm volatile("cp.async.wait_group 0;" ::: "memory"); }

__device__ __forceinline__ uint32_t smem_u32(const void* p) {
    uint32_t a;
    asm("{ .reg .u64 t; cvta.to.shared.u64 t, %1; cvt.u32.u64 %0, t; }" : "=r"(a) : "l"(p));
    return a;
}

// fp16 mma, fp32 accum
__device__ __forceinline__ void mma16(float* c, uint32_t a0, uint32_t a1,
                                      uint32_t a2, uint32_t a3,
                                      uint32_t b0, uint32_t b1) {
    asm volatile(
        "mma.sync.aligned.m16n8k16.row.col.f32.f16.f16.f32 "
        "{%0,%1,%2,%3},{%4,%5,%6,%7},{%8,%9},{%0,%1,%2,%3};"
        : "+f"(c[0]), "+f"(c[1]), "+f"(c[2]), "+f"(c[3])
        : "r"(a0), "r"(a1), "r"(a2), "r"(a3), "r"(b0), "r"(b1));
}

// ---------------- dtype detection / prep / CSR ----------------
__global__ void k_detect(const int* __restrict__ A) {
    __shared__ int nz;
    if (threadIdx.x == 0) nz = 0;
    __syncthreads();
    if (A[2 * threadIdx.x + 1] != 0) atomicOr(&nz, 1);
    __syncthreads();
    if (threadIdx.x == 0) g_is64 = (nz == 0) ? 1 : 0;
}

__global__ void k_prep(const void* __restrict__ Ab, const void* __restrict__ Ib) {
    int idx = blockIdx.x * blockDim.x + threadIdx.x;
    int is64 = g_is64;
    if (idx < 2 * NE) {
        long long v = is64 ? ((const long long*)Ab)[idx]
                           : (long long)((const int*)Ab)[idx];
        if (idx < NE) g_src[idx] = (int)v;
        else          g_dst[idx - NE] = (int)v;
    } else if (idx < 2 * NE + NN) {
        int i = idx - 2 * NE;
        long long v = is64 ? ((const long long*)Ib)[i]
                           : (long long)((const int*)Ib)[i];
        g_inp[i] = (int)v;
    } else if (idx < 2 * NE + NN + NN + 1) {
        g_rowptr[idx - 2 * NE - NN] = 0;
    }
}

// combined GRU biases: {bih_r+bhh_r, bih_z+bhh_z, bih_n, bhh_n} per column
__global__ void k_bias(const float* __restrict__ bih, const float* __restrict__ bhh) {
    int c = blockIdx.x * blockDim.x + threadIdx.x;
    if (c < HH) {
        float4 v;
        v.x = bih[c] + bhh[c];
        v.y = bih[c + HH] + bhh[c + HH];
        v.z = bih[c + 2 * HH];
        v.w = bhh[c + 2 * HH];
        *(float4*)&g_bias4[c][0] = v;
    }
}

// merged: x0h = fp16(emb[inputs])  AND  g_Bh[*][*][512:1024) = fp16(w_hh)
#define GX_N (NN * 64)
#define WH_N (G3 * (HH / 4))
__global__ void k_gxw(const float* __restrict__ emb, const float* __restrict__ whh) {
    int i = blockIdx.x * blockDim.x + threadIdx.x;
    if (i < GX_N) {
        int row = i >> 6, c = i & 63;
        const float4* src = (const float4*)(emb + (size_t)g_inp[row] * HH + c * 8);
        float4 v0 = src[0], v1 = src[1];
        __half2 h0 = __floats2half2_rn(v0.x, v0.y);
        __half2 h1 = __floats2half2_rn(v0.z, v0.w);
        __half2 h2 = __floats2half2_rn(v1.x, v1.y);
        __half2 h3 = __floats2half2_rn(v1.z, v1.w);
        uint4 u;
        u.x = *(uint32_t*)&h0; u.y = *(uint32_t*)&h1;
        u.z = *(uint32_t*)&h2; u.w = *(uint32_t*)&h3;
        *(uint4*)(g_x0h + (size_t)row * HH + c * 8) = u;
    } else {
        int j = i - GX_N;
        if (j < WH_N) {
            int row = j >> 7, c4 = j & 127;
            float4 v = ((const float4*)(whh + (size_t)row * HH))[c4];
            __half2 h0 = __floats2half2_rn(v.x, v.y);
            __half2 h1 = __floats2half2_rn(v.z, v.w);
            uint2 u = make_uint2(*(uint32_t*)&h0, *(uint32_t*)&h1);
            *(uint2*)&g_Bh[0][row][512 + c4 * 4] = u;
            *(uint2*)&g_Bh[1][row][512 + c4 * 4] = u;
        }
    }
}

__global__ void k_hist() {
    int e = blockIdx.x * blockDim.x + threadIdx.x;
    if (e < NE) atomicAdd(&g_rowptr[g_dst[e] + 1], 1);
}

// ---- multi-block scan of g_rowptr[1..NN] ----
__global__ void k_scan1() {  // grid 49, block 1024: per-block inclusive scan
    __shared__ int sh[1024];
    int t = threadIdx.x;
    int i = blockIdx.x * 1024 + t;
    int v = (i < NN) ? g_rowptr[i + 1] : 0;
    sh[t] = v;
    __syncthreads();
    for (int off = 1; off < 1024; off <<= 1) {
        int u = (t >= off) ? sh[t - off] : 0;
        __syncthreads();
        sh[t] += u;
        __syncthreads();
    }
    if (i < NN) g_rowptr[i + 1] = sh[t];
    if (t == 1023) g_bsum[blockIdx.x] = sh[1023];
}

__global__ void k_scan2() {  // parallel exclusive scan of 49 block sums
    __shared__ int sh[64];
    int t = threadIdx.x;
    int v = (t < 49) ? g_bsum[t] : 0;
    sh[t] = v;
    __syncthreads();
    for (int off = 1; off < 64; off <<= 1) {
        int u = (t >= off) ? sh[t - off] : 0;
        __syncthreads();
        sh[t] += u;
        __syncthreads();
    }
    if (t < 49) g_bsum[t] = sh[t] - v;   // exclusive
}

__global__ void k_scan3() {  // add block offsets; emit cursor in the same pass
    int i = blockIdx.x * 1024 + threadIdx.x;
    if (i < NN) {
        int v = g_rowptr[i + 1] + g_bsum[blockIdx.x];
        g_rowptr[i + 1] = v;
        if (i + 1 < NN) g_cursor[i + 1] = v;
        if (i == 0) g_cursor[0] = 0;
    }
}

__global__ void k_fill() {
    int e = blockIdx.x * blockDim.x + threadIdx.x;
    if (e < NE) {
        int p = atomicAdd(&g_cursor[g_dst[e]], 1);
        g_csr[p] = g_src[e];
    }
}

// S[node] = sum over in-edges of xh[src]; 4 nodes/block, 64 thr/node,
// 4-edge MLP batches (avg degree = 4)
__global__ void __launch_bounds__(256) k_gsum(int xsel) {
    const __half* __restrict__ X = xsel ? g_x1h : g_x0h;
    int node = blockIdx.x * 4 + (threadIdx.x >> 6);
    if (node >= NN) return;
    int t = threadIdx.x & 63;
    int beg = g_rowptr[node], end = g_rowptr[node + 1];
    float a[8];
#pragma unroll
    for (int q = 0; q < 8; q++) a[q] = 0.f;
    int j = beg;
    for (; j + 3 < end; j += 4) {
        int s0 = g_csr[j], s1 = g_csr[j + 1], s2 = g_csr[j + 2], s3 = g_csr[j + 3];
        uint4 u0 = *(const uint4*)(X + (size_t)s0 * HH + t * 8);
        uint4 u1 = *(const uint4*)(X + (size_t)s1 * HH + t * 8);
        uint4 u2 = *(const uint4*)(X + (size_t)s2 * HH + t * 8);
        uint4 u3 = *(const uint4*)(X + (size_t)s3 * HH + t * 8);
#pragma unroll
        for (int q = 0; q < 4; q++) {
            float2 f0 = __half22float2(*((__half2*)&u0 + q));
            float2 f1 = __half22float2(*((__half2*)&u1 + q));
            float2 f2 = __half22float2(*((__half2*)&u2 + q));
            float2 f3 = __half22float2(*((__half2*)&u3 + q));
            a[2 * q]     += (f0.x + f1.x) + (f2.x + f3.x);
            a[2 * q + 1] += (f0.y + f1.y) + (f2.y + f3.y);
        }
    }
    for (; j < end; j++) {
        int s0 = g_csr[j];
        uint4 u0 = *(const uint4*)(X + (size_t)s0 * HH + t * 8);
#pragma unroll
        for (int q = 0; q < 4; q++) {
            float2 f0 = __half22float2(*((__half2*)&u0 + q));
            a[2 * q] += f0.x;
            a[2 * q + 1] += f0.y;
        }
    }
    uint4 o;
    __half2 h0 = __floats2half2_rn(a[0], a[1]);
    __half2 h1 = __floats2half2_rn(a[2], a[3]);
    __half2 h2 = __floats2half2_rn(a[4], a[5]);
    __half2 h3 = __floats2half2_rn(a[6], a[7]);
    o.x = *(uint32_t*)&h0; o.y = *(uint32_t*)&h1;
    o.z = *(uint32_t*)&h2; o.w = *(uint32_t*)&h3;
    *(uint4*)(g_Sh + (size_t)node * HH + t * 8) = o;
}

// ---------------- g_Bh k<512 : Wp[l] = W_l @ w_ih^T (tf32 mma, transposed) --
// blockIdx.z = layer
__global__ void __launch_bounds__(256) k_wp(const float* __restrict__ Wbase,
                                            const float* __restrict__ Wih) {
    const int layer = blockIdx.z;
    const float* __restrict__ W = Wbase + (size_t)layer * HH * HH;
    __shared__ __align__(16) uint32_t As[64][36];
    __shared__ __align__(16) uint32_t Bs[32][36];
    const int tid = threadIdx.x;
    const int lane = tid & 31, wid = tid >> 5;
    const int wm = wid & 3, wn = wid >> 2;
    const int g8 = lane >> 2, t4 = lane & 3;
    const int i0 = blockIdx.y * 64;   // k index of Wp
    const int c0 = blockIdx.x * 32;   // gate col
    float acc[8];
#pragma unroll
    for (int b = 0; b < 8; b++) acc[b] = 0.f;

    for (int kt = 0; kt < 16; kt++) {
        const int kk0 = kt * 32;
        __syncthreads();
#pragma unroll
        for (int r2 = 0; r2 < 2; r2++) {
            int v = tid + 256 * r2;
            int row = v >> 3, c4 = v & 7;
            float4 a = *(const float4*)(W + (size_t)(i0 + row) * HH + kk0 + c4 * 4);
            uint4 u; u.x = f2tf(a.x); u.y = f2tf(a.y); u.z = f2tf(a.z); u.w = f2tf(a.w);
            *(uint4*)&As[row][c4 * 4] = u;
        }
        {
            int col = tid >> 3, k4 = tid & 7;
            float4 b = *(const float4*)(Wih + (size_t)(c0 + col) * HH + kk0 + k4 * 4);
            uint4 u; u.x = f2tf(b.x); u.y = f2tf(b.y); u.z = f2tf(b.z); u.w = f2tf(b.w);
            *(uint4*)&Bs[col][k4 * 4] = u;
        }
        __syncthreads();
#pragma unroll
        for (int ks = 0; ks < 4; ks++) {
            const int kb = ks * 8;
            uint32_t a0 = As[wm * 16 + g8][kb + t4];
            uint32_t a1 = As[wm * 16 + g8 + 8][kb + t4];
            uint32_t a2 = As[wm * 16 + g8][kb + t4 + 4];
            uint32_t a3 = As[wm * 16 + g8 + 8][kb + t4 + 4];
#pragma unroll
            for (int nt = 0; nt < 2; nt++) {
                int nc = wn * 16 + nt * 8 + g8;
                uint32_t b0 = Bs[nc][kb + t4];
                uint32_t b1 = Bs[nc][kb + t4 + 4];
                asm volatile(
                    "mma.sync.aligned.m16n8k8.row.col.f32.tf32.tf32.f32 "
                    "{%0,%1,%2,%3},{%4,%5,%6,%7},{%8,%9},{%0,%1,%2,%3};"
                    : "+f"(acc[nt * 4 + 0]), "+f"(acc[nt * 4 + 1]),
                      "+f"(acc[nt * 4 + 2]), "+f"(acc[nt * 4 + 3])
                    : "r"(a0), "r"(a1), "r"(a2), "r"(a3), "r"(b0), "r"(b1));
            }
        }
    }
#pragma unroll
    for (int nt = 0; nt < 2; nt++)
#pragma unroll
        for (int j = 0; j < 4; j++) {
            int krow = i0 + wm * 16 + g8 + ((j >> 1) << 3);
            int col = c0 + wn * 16 + nt * 8 + t4 * 2 + (j & 1);
            g_Bh[layer][col][krow] = __float2half_rn(acc[nt * 4 + j]);
        }
}

// ---------------- fused fp16 GEMM + GRU, merged K=1024, 3-stage pipeline ----
// Block tile: 128 m x 64 n-cols. 16 warps: wm=wid&3 (m32), wn=wid>>2 (n16).
// k-tile = 64 halves. 16 tiles (8 S-pass + 8 X-pass).
#define STRIDE_H 72                       // halves per smem row (64 + 8 pad)
#define ST_A (128 * STRIDE_H * 2)         // 18432 B
#define ST_B (192 * STRIDE_H * 2)         // 27648 B
#define ST_SZ (ST_A + ST_B)               // 46080 B
#define N_STAGE 3
#define SM_TOTAL (N_STAGE * ST_SZ)        // 138240 B

__global__ void __launch_bounds__(512, 1) k_fused(int layer, int xsel, int final_out,
                                                  float* __restrict__ dout,
                                                  const float* __restrict__ bih,
                                                  const float* __restrict__ bhh) {
    extern __shared__ __align__(16) char smem[];
    const uint32_t sbase = smem_u32(smem);

    const __half* __restrict__ Xh = xsel ? g_x1h : g_x0h;   // also the h-state
    const __half* __restrict__ Bh = &g_Bh[layer][0][0];

    const int tid = threadIdx.x;
    const int lane = tid & 31, wid = tid >> 5;
    const int wm = wid & 3, wn = wid >> 2;
    const int g8 = lane >> 2, t4 = lane & 3;
    const int i0 = blockIdx.y * 128;
    const int c0 = blockIdx.x * 64;

    float accR[2][2][4], accZ[2][2][4], accN1[2][2][4], accN2[2][2][4];
#pragma unroll
    for (int mf = 0; mf < 2; mf++)
#pragma unroll
        for (int nf = 0; nf < 2; nf++)
#pragma unroll
            for (int j = 0; j < 4; j++) {
                accR[mf][nf][j] = 0.f; accZ[mf][nf][j] = 0.f;
                accN1[mf][nf][j] = 0.f; accN2[mf][nf][j] = 0.f;
            }

    // ---- async tile loader: tile t in 0..15, pass = t>>3, kt = t&7 ----
    auto load_tile = [&](int s, int t) {
        const int pass = t >> 3;
        const int k0 = (t & 7) * 64;   // halves within the 512-half row
        const __half* Ap = pass ? Xh : g_Sh;
        const uint32_t sA = sbase + s * ST_SZ;
        const uint32_t sB = sA + ST_A;
#pragma unroll
        for (int i = 0; i < 2; i++) {   // A: 128 rows x 8 chunks of 16B
            int v = tid + 512 * i;
            int row = v >> 3, c = v & 7;
            int gr = i0 + row;
            if (gr >= NN) gr = NN - 1;  // dup rows discarded in epilogue
            const __half* src = Ap + (size_t)gr * HH + k0 + c * 8;
            cpasync16(sA + (uint32_t)(row * (STRIDE_H * 2) + c * 16), src);
        }
#pragma unroll
        for (int i = 0; i < 3; i++) {   // B: 192 cols x 8 chunks of 16B
            int v = tid + 512 * i;
            int col = v >> 3, c = v & 7;
            int gate = col >> 6, j = col & 63;
            const __half* src = Bh + (size_t)(gate * 512 + c0 + j) * 1024 +
                                pass * 512 + k0 + c * 8;
            cpasync16(sB + (uint32_t)(col * (STRIDE_H * 2) + c * 16), src);
        }
    };

    load_tile(0, 0);
    cp_commit();
    load_tile(1, 1);
    cp_commit();

    for (int t = 0; t < 16; t++) {
        if (t < 15) cp_wait1();   // tile t landed; t+1 still in flight
        else        cp_wait0();
        __syncthreads();          // all warps done with tile t-1's stage
        if (t + 2 < 16) {         // prefetch into stage (t+2)%3 (= stage of t-1)
            load_tile((t + 2) % N_STAGE, t + 2);
            cp_commit();
        }
        const int pass = t >> 3;
        const char* stg = smem + (t % N_STAGE) * ST_SZ;
        const __half* As = (const __half*)stg;
        const __half* Bs = (const __half*)(stg + ST_A);
#pragma unroll
        for (int ks = 0; ks < 4; ks++) {
            const int kb = ks * 16;
            uint32_t a[2][4];
#pragma unroll
            for (int mf = 0; mf < 2; mf++) {
                const __half* pa = As + (wm * 32 + mf * 16 + g8) * STRIDE_H + kb + 2 * t4;
                a[mf][0] = *(const uint32_t*)(pa);
                a[mf][1] = *(const uint32_t*)(pa + 8 * STRIDE_H);
                a[mf][2] = *(const uint32_t*)(pa + 8);
                a[mf][3] = *(const uint32_t*)(pa + 8 * STRIDE_H + 8);
            }
#pragma unroll
            for (int g = 0; g < 3; g++) {
#pragma unroll
                for (int nf = 0; nf < 2; nf++) {
                    int nc = wn * 16 + nf * 8 + g8;
                    const __half* pb = Bs + (g * 64 + nc) * STRIDE_H + kb + 2 * t4;
                    uint32_t b0 = *(const uint32_t*)(pb);
                    uint32_t b1 = *(const uint32_t*)(pb + 8);
#pragma unroll
                    for (int mf = 0; mf < 2; mf++) {
                        float* dst = (g == 0) ? accR[mf][nf]
                                   : (g == 1) ? accZ[mf][nf]
                                   : (pass == 0) ? accN1[mf][nf] : accN2[mf][nf];
                        mma16(dst, a[mf][0], a[mf][1], a[mf][2], a[mf][3], b0, b1);
                    }
                }
            }
        }
    }

    // ---- GRU epilogue: h from fp16 Xh, biases from packed g_bias4 ----
    float4 bq[2][2];  // [nf][q] combined biases per column
#pragma unroll
    for (int nf = 0; nf < 2; nf++)
#pragma unroll
        for (int q = 0; q < 2; q++)
            bq[nf][q] = *(const float4*)&g_bias4[c0 + wn * 16 + nf * 8 + t4 * 2 + q][0];

#pragma unroll
    for (int mf = 0; mf < 2; mf++)
#pragma unroll
        for (int nf = 0; nf < 2; nf++) {
            const int colb = c0 + wn * 16 + nf * 8 + t4 * 2;
#pragma unroll
            for (int half_ = 0; half_ < 2; half_++) {   // j pair: rows g8 / g8+8
                int row = i0 + wm * 32 + mf * 16 + g8 + half_ * 8;
                if (row < NN) {
                    uint32_t hu = *(const uint32_t*)(Xh + (size_t)row * HH + colb);
                    float2 hv = __half22float2(*(__half2*)&hu);
                    float o[2];
#pragma unroll
                    for (int q = 0; q < 2; q++) {
                        int j = half_ * 2 + q;
                        float4 bb = bq[nf][q];
                        float r = sigm(accR[mf][nf][j] + bb.x);
                        float z = sigm(accZ[mf][nf][j] + bb.y);
                        float n = tanh_fast(accN1[mf][nf][j] + bb.z +
                                            r * (accN2[mf][nf][j] + bb.w));
                        float h = (q == 0) ? hv.x : hv.y;
                        o[q] = (1.f - z) * n + z * h;
                    }
                    if (final_out) {
                        *(float2*)(dout + (size_t)row * HH + colb) = make_float2(o[0], o[1]);
                    } else {
                        __half2 hh = __floats2half2_rn(o[0], o[1]);
                        *(uint32_t*)(g_x1h + (size_t)row * HH + colb) = *(uint32_t*)&hh;
                    }
                }
            }
        }
}

// ---------------- launch ----------------
extern "C" void kernel_launch(void* const* d_in, const int* in_sizes, int n_in,
                              void* d_out, int out_size) {
    const void* inputs = d_in[0];
    const void* A      = d_in[1];
    const float* emb    = (const float*)d_in[2];
    const float* weight = (const float*)d_in[3];
    const float* w_ih   = (const float*)d_in[4];
    const float* w_hh   = (const float*)d_in[5];
    const float* b_ih   = (const float*)d_in[6];
    const float* b_hh   = (const float*)d_in[7];
    float* out = (float*)d_out;

    cudaFuncSetAttribute(k_fused, cudaFuncAttributeMaxDynamicSharedMemorySize, SM_TOTAL);

    k_detect<<<1, 128>>>((const int*)A);
    k_bias<<<2, 256>>>(b_ih, b_hh);
    int T = 2 * NE + NN + NN + 1;
    k_prep<<<(T + 255) / 256, 256>>>(A, inputs);
    k_gxw<<<(GX_N + WH_N + 255) / 256, 256>>>(emb, w_hh);
    k_hist<<<(NE + 255) / 256, 256>>>();
    k_scan1<<<49, 1024>>>();
    k_scan2<<<1, 64>>>();
    k_scan3<<<49, 1024>>>();
    k_fill<<<(NE + 255) / 256, 256>>>();
    k_wp<<<dim3(G3 / 32, HH / 64, 2), 256>>>(weight, w_ih);
    k_gsum<<<(NN + 3) / 4, 256>>>(0);
    k_fused<<<dim3(HH / 64, (NN + 127) / 128), 512, SM_TOTAL>>>(
        0, 0, 0, out, b_ih, b_hh);
    k_gsum<<<(NN + 3) / 4, 256>>>(1);
    k_fused<<<dim3(HH / 64, (NN + 127) / 128), 512, SM_TOTAL>>>(
        1, 1, 1, out, b_ih, b_hh);
}

// round 16
// speedup vs baseline: 1.1857x; 1.0100x over previous
#include <cuda_runtime.h>
#include <cuda_fp16.h>
#include <cstdint>

#define NN 50000
#define NE 200000
#define HH 512
#define G3 1536

// ---------------- device scratch (static, no allocation) ----------------
__device__ int g_is64;
__device__ int g_src[NE];
__device__ int g_dst[NE];
__device__ int g_inp[NN];
__device__ int g_rowptr[NN + 1];
__device__ int g_cursor[NN];
__device__ int g_csr[NE];
__device__ int g_bsum[64];
__device__ __align__(16) float g_bias4[HH][4];           // {br, bz, b_in, b_hn}
__device__ __align__(128) __half g_x0h[(size_t)NN * HH]; // fp16 node states
__device__ __align__(128) __half g_x1h[(size_t)NN * HH];
__device__ __align__(128) __half g_Sh[(size_t)NN * HH];
// g_Bh[l][gatecol][k] col-major fp16: cols 0..511 = r, 512..1023 = z, 1024..1535 = n
// k 0..511 = Wp (S pass), 512..1023 = w_hh (X pass)
__device__ __align__(128) __half g_Bh[2][G3][1024];

// ---------------- helpers ----------------
__device__ __forceinline__ uint32_t f2tf(float f) {
    uint32_t u;
    asm("cvt.rna.tf32.f32 %0, %1;" : "=r"(u) : "f"(f));
    return u;
}
__device__ __forceinline__ float sigm(float v) { return 1.f / (1.f + __expf(-v)); }
__device__ __forceinline__ float tanh_fast(float v) { return 1.f - 2.f / (__expf(2.f * v) + 1.f); }

__device__ __forceinline__ void cpasync16(uint32_t d, const void* s) {
    asm volatile("cp.async.cg.shared.global [%0], [%1], 16;" :: "r"(d), "l"(s));
}
__device__ __forceinline__ void cp_commit() { asm volatile("cp.async.commit_group;"); }
__device__ __forceinline__ void cp_wait1() { asm volatile("cp.async.wait_group 1;" ::: "memory"); }
__device__ __forceinline__ void cp_wait0() { asm volatile("cp.async.wait_group 0;" ::: "memory"); }

__device__ __forceinline__ uint32_t smem_u32(const void* p) {
    uint32_t a;
    asm("{ .reg .u64 t; cvta.to.shared.u64 t, %1; cvt.u32.u64 %0, t; }" : "=r"(a) : "l"(p));
    return a;
}

// fp16 mma, fp32 accum
__device__ __forceinline__ void mma16(float* c, uint32_t a0, uint32_t a1,
                                      uint32_t a2, uint32_t a3,
                                      uint32_t b0, uint32_t b1) {
    asm volatile(
        "mma.sync.aligned.m16n8k16.row.col.f32.f16.f16.f32 "
        "{%0,%1,%2,%3},{%4,%5,%6,%7},{%8,%9},{%0,%1,%2,%3};"
        : "+f"(c[0]), "+f"(c[1]), "+f"(c[2]), "+f"(c[3])
        : "r"(a0), "r"(a1), "r"(a2), "r"(a3), "r"(b0), "r"(b1));
}

// ---------------- detect dtype + zero rowptr ----------------
__global__ void k_detect(const int* __restrict__ A) {
    int i = blockIdx.x * blockDim.x + threadIdx.x;
    if (i < NN + 1) g_rowptr[i] = 0;
    if (blockIdx.x == 0) {
        __shared__ int nz;
        if (threadIdx.x == 0) nz = 0;
        __syncthreads();
        if (threadIdx.x < 128 && A[2 * threadIdx.x + 1] != 0) atomicOr(&nz, 1);
        __syncthreads();
        if (threadIdx.x == 0) g_is64 = (nz == 0) ? 1 : 0;
    }
}

// convert edges + inputs; histogram fused (rowptr pre-zeroed by k_detect)
__global__ void k_prep(const void* __restrict__ Ab, const void* __restrict__ Ib) {
    int idx = blockIdx.x * blockDim.x + threadIdx.x;
    int is64 = g_is64;
    if (idx < 2 * NE) {
        long long v = is64 ? ((const long long*)Ab)[idx]
                           : (long long)((const int*)Ab)[idx];
        if (idx < NE) {
            g_src[idx] = (int)v;
        } else {
            g_dst[idx - NE] = (int)v;
            atomicAdd(&g_rowptr[(int)v + 1], 1);
        }
    } else if (idx < 2 * NE + NN) {
        int i = idx - 2 * NE;
        long long v = is64 ? ((const long long*)Ib)[i]
                           : (long long)((const int*)Ib)[i];
        g_inp[i] = (int)v;
    }
}

// combined GRU biases: {bih_r+bhh_r, bih_z+bhh_z, bih_n, bhh_n} per column
__global__ void k_bias(const float* __restrict__ bih, const float* __restrict__ bhh) {
    int c = blockIdx.x * blockDim.x + threadIdx.x;
    if (c < HH) {
        float4 v;
        v.x = bih[c] + bhh[c];
        v.y = bih[c + HH] + bhh[c + HH];
        v.z = bih[c + 2 * HH];
        v.w = bhh[c + 2 * HH];
        *(float4*)&g_bias4[c][0] = v;
    }
}

// merged: x0h = fp16(emb[inputs])  AND  g_Bh[*][*][512:1024) = fp16(w_hh)
#define GX_N (NN * 64)
#define WH_N (G3 * (HH / 4))
__global__ void k_gxw(const float* __restrict__ emb, const float* __restrict__ whh) {
    int i = blockIdx.x * blockDim.x + threadIdx.x;
    if (i < GX_N) {
        int row = i >> 6, c = i & 63;
        const float4* src = (const float4*)(emb + (size_t)g_inp[row] * HH + c * 8);
        float4 v0 = src[0], v1 = src[1];
        __half2 h0 = __floats2half2_rn(v0.x, v0.y);
        __half2 h1 = __floats2half2_rn(v0.z, v0.w);
        __half2 h2 = __floats2half2_rn(v1.x, v1.y);
        __half2 h3 = __floats2half2_rn(v1.z, v1.w);
        uint4 u;
        u.x = *(uint32_t*)&h0; u.y = *(uint32_t*)&h1;
        u.z = *(uint32_t*)&h2; u.w = *(uint32_t*)&h3;
        *(uint4*)(g_x0h + (size_t)row * HH + c * 8) = u;
    } else {
        int j = i - GX_N;
        if (j < WH_N) {
            int row = j >> 7, c4 = j & 127;
            float4 v = ((const float4*)(whh + (size_t)row * HH))[c4];
            __half2 h0 = __floats2half2_rn(v.x, v.y);
            __half2 h1 = __floats2half2_rn(v.z, v.w);
            uint2 u = make_uint2(*(uint32_t*)&h0, *(uint32_t*)&h1);
            *(uint2*)&g_Bh[0][row][512 + c4 * 4] = u;
            *(uint2*)&g_Bh[1][row][512 + c4 * 4] = u;
        }
    }
}

// ---- multi-block scan of g_rowptr[1..NN] ----
__global__ void k_scan1() {  // grid 49, block 1024: per-block inclusive scan
    __shared__ int sh[1024];
    int t = threadIdx.x;
    int i = blockIdx.x * 1024 + t;
    int v = (i < NN) ? g_rowptr[i + 1] : 0;
    sh[t] = v;
    __syncthreads();
    for (int off = 1; off < 1024; off <<= 1) {
        int u = (t >= off) ? sh[t - off] : 0;
        __syncthreads();
        sh[t] += u;
        __syncthreads();
    }
    if (i < NN) g_rowptr[i + 1] = sh[t];
    if (t == 1023) g_bsum[blockIdx.x] = sh[1023];
}

__global__ void k_scan2() {  // parallel exclusive scan of 49 block sums
    __shared__ int sh[64];
    int t = threadIdx.x;
    int v = (t < 49) ? g_bsum[t] : 0;
    sh[t] = v;
    __syncthreads();
    for (int off = 1; off < 64; off <<= 1) {
        int u = (t >= off) ? sh[t - off] : 0;
        __syncthreads();
        sh[t] += u;
        __syncthreads();
    }
    if (t < 49) g_bsum[t] = sh[t] - v;   // exclusive
}

__global__ void k_scan3() {  // add block offsets; emit cursor in the same pass
    int i = blockIdx.x * 1024 + threadIdx.x;
    if (i < NN) {
        int v = g_rowptr[i + 1] + g_bsum[blockIdx.x];
        g_rowptr[i + 1] = v;
        if (i + 1 < NN) g_cursor[i + 1] = v;
        if (i == 0) g_cursor[0] = 0;
    }
}

__global__ void k_fill() {
    int e = blockIdx.x * blockDim.x + threadIdx.x;
    if (e < NE) {
        int p = atomicAdd(&g_cursor[g_dst[e]], 1);
        g_csr[p] = g_src[e];
    }
}

// S[node] = sum over in-edges of xh[src]; 4 nodes/block, 64 thr/node,
// 4-edge MLP batches (avg degree = 4)
__global__ void __launch_bounds__(256) k_gsum(int xsel) {
    const __half* __restrict__ X = xsel ? g_x1h : g_x0h;
    int node = blockIdx.x * 4 + (threadIdx.x >> 6);
    if (node >= NN) return;
    int t = threadIdx.x & 63;
    int beg = g_rowptr[node], end = g_rowptr[node + 1];
    float a[8];
#pragma unroll
    for (int q = 0; q < 8; q++) a[q] = 0.f;
    int j = beg;
    for (; j + 3 < end; j += 4) {
        int s0 = g_csr[j], s1 = g_csr[j + 1], s2 = g_csr[j + 2], s3 = g_csr[j + 3];
        uint4 u0 = *(const uint4*)(X + (size_t)s0 * HH + t * 8);
        uint4 u1 = *(const uint4*)(X + (size_t)s1 * HH + t * 8);
        uint4 u2 = *(const uint4*)(X + (size_t)s2 * HH + t * 8);
        uint4 u3 = *(const uint4*)(X + (size_t)s3 * HH + t * 8);
#pragma unroll
        for (int q = 0; q < 4; q++) {
            float2 f0 = __half22float2(*((__half2*)&u0 + q));
            float2 f1 = __half22float2(*((__half2*)&u1 + q));
            float2 f2 = __half22float2(*((__half2*)&u2 + q));
            float2 f3 = __half22float2(*((__half2*)&u3 + q));
            a[2 * q]     += (f0.x + f1.x) + (f2.x + f3.x);
            a[2 * q + 1] += (f0.y + f1.y) + (f2.y + f3.y);
        }
    }
    for (; j < end; j++) {
        int s0 = g_csr[j];
        uint4 u0 = *(const uint4*)(X + (size_t)s0 * HH + t * 8);
#pragma unroll
        for (int q = 0; q < 4; q++) {
            float2 f0 = __half22float2(*((__half2*)&u0 + q));
            a[2 * q] += f0.x;
            a[2 * q + 1] += f0.y;
        }
    }
    uint4 o;
    __half2 h0 = __floats2half2_rn(a[0], a[1]);
    __half2 h1 = __floats2half2_rn(a[2], a[3]);
    __half2 h2 = __floats2half2_rn(a[4], a[5]);
    __half2 h3 = __floats2half2_rn(a[6], a[7]);
    o.x = *(uint32_t*)&h0; o.y = *(uint32_t*)&h1;
    o.z = *(uint32_t*)&h2; o.w = *(uint32_t*)&h3;
    *(uint4*)(g_Sh + (size_t)node * HH + t * 8) = o;
}

// ---------------- g_Bh k<512 : Wp[l] = W_l @ w_ih^T (tf32 mma, transposed) --
// blockIdx.z = layer
__global__ void __launch_bounds__(256) k_wp(const float* __restrict__ Wbase,
                                            const float* __restrict__ Wih) {
    const int layer = blockIdx.z;
    const float* __restrict__ W = Wbase + (size_t)layer * HH * HH;
    __shared__ __align__(16) uint32_t As[64][36];
    __shared__ __align__(16) uint32_t Bs[32][36];
    const int tid = threadIdx.x;
    const int lane = tid & 31, wid = tid >> 5;
    const int wm = wid & 3, wn = wid >> 2;
    const int g8 = lane >> 2, t4 = lane & 3;
    const int i0 = blockIdx.y * 64;   // k index of Wp
    const int c0 = blockIdx.x * 32;   // gate col
    float acc[8];
#pragma unroll
    for (int b = 0; b < 8; b++) acc[b] = 0.f;

    for (int kt = 0; kt < 16; kt++) {
        const int kk0 = kt * 32;
        __syncthreads();
#pragma unroll
        for (int r2 = 0; r2 < 2; r2++) {
            int v = tid + 256 * r2;
            int row = v >> 3, c4 = v & 7;
            float4 a = *(const float4*)(W + (size_t)(i0 + row) * HH + kk0 + c4 * 4);
            uint4 u; u.x = f2tf(a.x); u.y = f2tf(a.y); u.z = f2tf(a.z); u.w = f2tf(a.w);
            *(uint4*)&As[row][c4 * 4] = u;
        }
        {
            int col = tid >> 3, k4 = tid & 7;
            float4 b = *(const float4*)(Wih + (size_t)(c0 + col) * HH + kk0 + k4 * 4);
            uint4 u; u.x = f2tf(b.x); u.y = f2tf(b.y); u.z = f2tf(b.z); u.w = f2tf(b.w);
            *(uint4*)&Bs[col][k4 * 4] = u;
        }
        __syncthreads();
#pragma unroll
        for (int ks = 0; ks < 4; ks++) {
            const int kb = ks * 8;
            uint32_t a0 = As[wm * 16 + g8][kb + t4];
            uint32_t a1 = As[wm * 16 + g8 + 8][kb + t4];
            uint32_t a2 = As[wm * 16 + g8][kb + t4 + 4];
            uint32_t a3 = As[wm * 16 + g8 + 8][kb + t4 + 4];
#pragma unroll
            for (int nt = 0; nt < 2; nt++) {
                int nc = wn * 16 + nt * 8 + g8;
                uint32_t b0 = Bs[nc][kb + t4];
                uint32_t b1 = Bs[nc][kb + t4 + 4];
                asm volatile(
                    "mma.sync.aligned.m16n8k8.row.col.f32.tf32.tf32.f32 "
                    "{%0,%1,%2,%3},{%4,%5,%6,%7},{%8,%9},{%0,%1,%2,%3};"
                    : "+f"(acc[nt * 4 + 0]), "+f"(acc[nt * 4 + 1]),
                      "+f"(acc[nt * 4 + 2]), "+f"(acc[nt * 4 + 3])
                    : "r"(a0), "r"(a1), "r"(a2), "r"(a3), "r"(b0), "r"(b1));
            }
        }
    }
#pragma unroll
    for (int nt = 0; nt < 2; nt++)
#pragma unroll
        for (int j = 0; j < 4; j++) {
            int krow = i0 + wm * 16 + g8 + ((j >> 1) << 3);
            int col = c0 + wn * 16 + nt * 8 + t4 * 2 + (j & 1);
            g_Bh[layer][col][krow] = __float2half_rn(acc[nt * 4 + j]);
        }
}

// ---------------- fused fp16 GEMM + GRU, merged K=1024, 3-stage pipeline ----
// Block tile: 128 m x 64 n-cols. 16 warps: wm=wid&3 (m32), wn=wid>>2 (n16).
// k-tile = 64 halves. 16 tiles (8 S-pass + 8 X-pass).
#define STRIDE_H 72                       // halves per smem row (64 + 8 pad)
#define ST_A (128 * STRIDE_H * 2)         // 18432 B
#define ST_B (192 * STRIDE_H * 2)         // 27648 B
#define ST_SZ (ST_A + ST_B)               // 46080 B
#define N_STAGE 3
#define SM_TOTAL (N_STAGE * ST_SZ)        // 138240 B

__global__ void __launch_bounds__(512, 1) k_fused(int layer, int xsel, int final_out,
                                                  float* __restrict__ dout,
                                                  const float* __restrict__ bih,
                                                  const float* __restrict__ bhh) {
    extern __shared__ __align__(16) char smem[];
    const uint32_t sbase = smem_u32(smem);

    const __half* __restrict__ Xh = xsel ? g_x1h : g_x0h;   // also the h-state
    const __half* __restrict__ Bh = &g_Bh[layer][0][0];

    const int tid = threadIdx.x;
    const int lane = tid & 31, wid = tid >> 5;
    const int wm = wid & 3, wn = wid >> 2;
    const int g8 = lane >> 2, t4 = lane & 3;
    const int i0 = blockIdx.y * 128;
    const int c0 = blockIdx.x * 64;

    float accR[2][2][4], accZ[2][2][4], accN1[2][2][4], accN2[2][2][4];
#pragma unroll
    for (int mf = 0; mf < 2; mf++)
#pragma unroll
        for (int nf = 0; nf < 2; nf++)
#pragma unroll
            for (int j = 0; j < 4; j++) {
                accR[mf][nf][j] = 0.f; accZ[mf][nf][j] = 0.f;
                accN1[mf][nf][j] = 0.f; accN2[mf][nf][j] = 0.f;
            }

    // ---- async tile loader: tile t in 0..15, pass = t>>3, kt = t&7 ----
    auto load_tile = [&](int s, int t) {
        const int pass = t >> 3;
        const int k0 = (t & 7) * 64;   // halves within the 512-half row
        const __half* Ap = pass ? Xh : g_Sh;
        const uint32_t sA = sbase + s * ST_SZ;
        const uint32_t sB = sA + ST_A;
#pragma unroll
        for (int i = 0; i < 2; i++) {   // A: 128 rows x 8 chunks of 16B
            int v = tid + 512 * i;
            int row = v >> 3, c = v & 7;
            int gr = i0 + row;
            if (gr >= NN) gr = NN - 1;  // dup rows discarded in epilogue
            const __half* src = Ap + (size_t)gr * HH + k0 + c * 8;
            cpasync16(sA + (uint32_t)(row * (STRIDE_H * 2) + c * 16), src);
        }
#pragma unroll
        for (int i = 0; i < 3; i++) {   // B: 192 cols x 8 chunks of 16B
            int v = tid + 512 * i;
            int col = v >> 3, c = v & 7;
            int gate = col >> 6, j = col & 63;
            const __half* src = Bh + (size_t)(gate * 512 + c0 + j) * 1024 +
                                pass * 512 + k0 + c * 8;
            cpasync16(sB + (uint32_t)(col * (STRIDE_H * 2) + c * 16), src);
        }
    };

    load_tile(0, 0);
    cp_commit();
    load_tile(1, 1);
    cp_commit();

    for (int t = 0; t < 16; t++) {
        if (t < 15) cp_wait1();   // tile t landed; t+1 still in flight
        else        cp_wait0();
        __syncthreads();          // all warps done with tile t-1's stage
        if (t + 2 < 16) {         // prefetch into stage (t+2)%3 (= stage of t-1)
            load_tile((t + 2) % N_STAGE, t + 2);
            cp_commit();
        }
        const int pass = t >> 3;
        const char* stg = smem + (t % N_STAGE) * ST_SZ;
        const __half* As = (const __half*)stg;
        const __half* Bs = (const __half*)(stg + ST_A);
#pragma unroll
        for (int ks = 0; ks < 4; ks++) {
            const int kb = ks * 16;
            uint32_t a[2][4];
#pragma unroll
            for (int mf = 0; mf < 2; mf++) {
                const __half* pa = As + (wm * 32 + mf * 16 + g8) * STRIDE_H + kb + 2 * t4;
                a[mf][0] = *(const uint32_t*)(pa);
                a[mf][1] = *(const uint32_t*)(pa + 8 * STRIDE_H);
                a[mf][2] = *(const uint32_t*)(pa + 8);
                a[mf][3] = *(const uint32_t*)(pa + 8 * STRIDE_H + 8);
            }
#pragma unroll
            for (int g = 0; g < 3; g++) {
#pragma unroll
                for (int nf = 0; nf < 2; nf++) {
                    int nc = wn * 16 + nf * 8 + g8;
                    const __half* pb = Bs + (g * 64 + nc) * STRIDE_H + kb + 2 * t4;
                    uint32_t b0 = *(const uint32_t*)(pb);
                    uint32_t b1 = *(const uint32_t*)(pb + 8);
#pragma unroll
                    for (int mf = 0; mf < 2; mf++) {
                        float* dst = (g == 0) ? accR[mf][nf]
                                   : (g == 1) ? accZ[mf][nf]
                                   : (pass == 0) ? accN1[mf][nf] : accN2[mf][nf];
                        mma16(dst, a[mf][0], a[mf][1], a[mf][2], a[mf][3], b0, b1);
                    }
                }
            }
        }
    }

    // ---- GRU epilogue: h from fp16 Xh, biases from packed g_bias4 ----
    float4 bq[2][2];  // [nf][q] combined biases per column
#pragma unroll
    for (int nf = 0; nf < 2; nf++)
#pragma unroll
        for (int q = 0; q < 2; q++)
            bq[nf][q] = *(const float4*)&g_bias4[c0 + wn * 16 + nf * 8 + t4 * 2 + q][0];

#pragma unroll
    for (int mf = 0; mf < 2; mf++)
#pragma unroll
        for (int nf = 0; nf < 2; nf++) {
            const int colb = c0 + wn * 16 + nf * 8 + t4 * 2;
#pragma unroll
            for (int half_ = 0; half_ < 2; half_++) {   // j pair: rows g8 / g8+8
                int row = i0 + wm * 32 + mf * 16 + g8 + half_ * 8;
                if (row < NN) {
                    uint32_t hu = *(const uint32_t*)(Xh + (size_t)row * HH + colb);
                    float2 hv = __half22float2(*(__half2*)&hu);
                    float o[2];
#pragma unroll
                    for (int q = 0; q < 2; q++) {
                        int j = half_ * 2 + q;
                        float4 bb = bq[nf][q];
                        float r = sigm(accR[mf][nf][j] + bb.x);
                        float z = sigm(accZ[mf][nf][j] + bb.y);
                        float n = tanh_fast(accN1[mf][nf][j] + bb.z +
                                            r * (accN2[mf][nf][j] + bb.w));
                        float h = (q == 0) ? hv.x : hv.y;
                        o[q] = (1.f - z) * n + z * h;
                    }
                    if (final_out) {
                        *(float2*)(dout + (size_t)row * HH + colb) = make_float2(o[0], o[1]);
                    } else {
                        __half2 hh = __floats2half2_rn(o[0], o[1]);
                        *(uint32_t*)(g_x1h + (size_t)row * HH + colb) = *(uint32_t*)&hh;
                    }
                }
            }
        }
}

// ---------------- launch ----------------
extern "C" void kernel_launch(void* const* d_in, const int* in_sizes, int n_in,
                              void* d_out, int out_size) {
    const void* inputs = d_in[0];
    const void* A      = d_in[1];
    const float* emb    = (const float*)d_in[2];
    const float* weight = (const float*)d_in[3];
    const float* w_ih   = (const float*)d_in[4];
    const float* w_hh   = (const float*)d_in[5];
    const float* b_ih   = (const float*)d_in[6];
    const float* b_hh   = (const float*)d_in[7];
    float* out = (float*)d_out;

    // side streams / events: created once on the first (non-captured) call
    static cudaStream_t sB = nullptr, sC = nullptr;
    static cudaEvent_t evFork = nullptr, evPrep = nullptr, evB = nullptr, evC = nullptr;
    if (sB == nullptr) {
        cudaStreamCreateWithFlags(&sB, cudaStreamNonBlocking);
        cudaStreamCreateWithFlags(&sC, cudaStreamNonBlocking);
        cudaEventCreateWithFlags(&evFork, cudaEventDisableTiming);
        cudaEventCreateWithFlags(&evPrep, cudaEventDisableTiming);
        cudaEventCreateWithFlags(&evB, cudaEventDisableTiming);
        cudaEventCreateWithFlags(&evC, cudaEventDisableTiming);
        cudaFuncSetAttribute(k_fused, cudaFuncAttributeMaxDynamicSharedMemorySize, SM_TOTAL);
    }

    // fork: stream B runs weight-prep GEMM (independent of all inputs prep)
    cudaEventRecord(evFork, 0);
    cudaStreamWaitEvent(sB, evFork, 0);
    k_wp<<<dim3(G3 / 32, HH / 64, 2), 256, 0, sB>>>(weight, w_ih);
    k_bias<<<2, 256, 0, sB>>>(b_ih, b_hh);
    cudaEventRecord(evB, sB);

    // stream 0: detect -> prep(+hist)
    k_detect<<<(NN + 256) / 256, 256>>>((const int*)A);
    int T = 2 * NE + NN;
    k_prep<<<(T + 255) / 256, 256>>>(A, inputs);
    cudaEventRecord(evPrep, 0);

    // stream C: embedding gather + whh copy (needs g_inp from prep)
    cudaStreamWaitEvent(sC, evPrep, 0);
    k_gxw<<<(GX_N + WH_N + 255) / 256, 256, 0, sC>>>(emb, w_hh);
    cudaEventRecord(evC, sC);

    // stream 0: CSR build (concurrent with B and C)
    k_scan1<<<49, 1024>>>();
    k_scan2<<<1, 64>>>();
    k_scan3<<<49, 1024>>>();
    k_fill<<<(NE + 255) / 256, 256>>>();

    // join: gsum needs x0h (C); fused needs Bh/bias (B)
    cudaStreamWaitEvent(0, evC, 0);
    k_gsum<<<(NN + 3) / 4, 256>>>(0);
    cudaStreamWaitEvent(0, evB, 0);
    k_fused<<<dim3(HH / 64, (NN + 127) / 128), 512, SM_TOTAL>>>(
        0, 0, 0, out, b_ih, b_hh);
    k_gsum<<<(NN + 3) / 4, 256>>>(1);
    k_fused<<<dim3(HH / 64, (NN + 127) / 128), 512, SM_TOTAL>>>(
        1, 1, 1, out, b_ih, b_hh);
}